// round 1
// baseline (speedup 1.0000x reference)
#include <cuda_runtime.h>

#define BB_   64
#define DIN_  512
#define HH_   512

// Per-h precomputed scalars (H = 512 floats each; 16B aligned for float4 loads)
__device__ __align__(16) float g_arr[HH_];
__device__ __align__(16) float phi_arr[HH_];
__device__ __align__(16) float norm_arr[HH_];

// ---------------------------------------------------------------------------
// K1: compute g, phi, norm per h (one block of 512 threads)
// ---------------------------------------------------------------------------
__global__ void scalars_kernel(const float* __restrict__ r_param,
                               const float* __restrict__ theta_param) {
    int h = threadIdx.x;
    float rp = r_param[h];
    float tp = theta_param[h];
    float exp_r = expf(rp);
    float r     = expf(-exp_r);
    float theta = expf(tp);
    float g   = r * cosf(theta);
    float phi = r * sinf(theta);
    float nrm = sqrtf(1.0f - r * r);
    g_arr[h]    = g;
    phi_arr[h]  = phi;
    norm_arr[h] = nrm;
}

// ---------------------------------------------------------------------------
// K2: fused small GEMM (x_t @ wx1, x_t @ wx2) + epilogue producing
//     h_t_c1, h_t_c2, n0, n1, n2, n3  (each B x H)
// Grid: (B/4, H/128), block 128 threads. Each block handles 4 batch rows
// and 128 h-columns; wx is read 16x total (L2-resident).
// ---------------------------------------------------------------------------
__global__ void gemm_small_kernel(const float* __restrict__ x_t,
                                  const float* __restrict__ h_c1,
                                  const float* __restrict__ h_c2,
                                  const float* __restrict__ gm0,
                                  const float* __restrict__ gm1,
                                  const float* __restrict__ gm2,
                                  const float* __restrict__ gm3,
                                  const float* __restrict__ r_param,
                                  const float* __restrict__ theta_param,
                                  const float* __restrict__ wx1,
                                  const float* __restrict__ wx2,
                                  float* __restrict__ out) {
    const int BT = 4;  // batch rows per block
    __shared__ float sx[BT][DIN_];

    int b0 = blockIdx.x * BT;
    int h  = blockIdx.y * 128 + threadIdx.x;

    // Stage the 4 x_t rows into shared memory (coalesced)
    for (int i = threadIdx.x; i < BT * DIN_; i += 128) {
        int bb = i >> 9;           // / 512
        int d  = i & (DIN_ - 1);   // % 512
        sx[bb][d] = x_t[(b0 + bb) * DIN_ + d];
    }
    __syncthreads();

    float acc1[BT] = {0.f, 0.f, 0.f, 0.f};
    float acc2[BT] = {0.f, 0.f, 0.f, 0.f};

#pragma unroll 4
    for (int d = 0; d < DIN_; d++) {
        float w1 = wx1[d * HH_ + h];
        float w2 = wx2[d * HH_ + h];
#pragma unroll
        for (int bb = 0; bb < BT; bb++) {
            float xv = sx[bb][d];
            acc1[bb] = fmaf(xv, w1, acc1[bb]);
            acc2[bb] = fmaf(xv, w2, acc2[bb]);
        }
    }

    // Per-h scalars (each thread owns one h; ~10 transcendental ops, negligible)
    float rp    = r_param[h];
    float tp    = theta_param[h];
    float exp_r = expf(rp);
    float r     = expf(-exp_r);
    float theta = expf(tp);
    float g     = r * cosf(theta);
    float phi   = r * sinf(theta);
    float rr    = r * r;
    float nrm   = sqrtf(1.0f - rr);
    float d_g_w_r       = -exp_r * g;
    float d_phi_w_r     = -exp_r * phi;
    float d_g_w_theta   = -theta * phi;
    float d_phi_w_theta =  theta * g;
    float d_norm_w_r    =  exp_r * rr / nrm;

    const int SZ = BB_ * HH_;  // 32768 elements per small tensor

#pragma unroll
    for (int bb = 0; bb < BT; bb++) {
        int idx = (b0 + bb) * HH_ + h;
        float hc1 = h_c1[idx];
        float hc2 = h_c2[idx];
        float m0 = gm0[idx], m1 = gm1[idx], m2 = gm2[idx], m3 = gm3[idx];
        float w1x = acc1[bb];
        float w2x = acc2[bb];

        out[0 * SZ + idx] = g * hc1 - phi * hc2 + nrm * w1x;                                     // h_t_c1
        out[1 * SZ + idx] = g * hc2 + phi * hc1 + nrm * w2x;                                     // h_t_c2
        out[2 * SZ + idx] = d_g_w_r * hc1 + g * m0 - d_phi_w_r * hc2 - phi * m1 + d_norm_w_r * w1x;  // n0
        out[3 * SZ + idx] = d_g_w_r * hc2 + g * m1 + d_phi_w_r * hc1 + phi * m0 + d_norm_w_r * w2x;  // n1
        out[4 * SZ + idx] = d_g_w_theta * hc1 + g * m2 - d_phi_w_theta * hc2 - phi * m3;         // n2
        out[5 * SZ + idx] = d_g_w_theta * hc2 + g * m3 + d_phi_w_theta * hc1 + phi * m2;         // n3
    }
}

// ---------------------------------------------------------------------------
// K3: the HBM-bound streaming kernel for n4..n7 (each B x D_IN x H).
// float4-vectorized along h. Per thread: 4 float4 gm loads, 4 float4 stores,
// x scalar (L2-broadcast), g/phi/norm float4 (L1-resident device arrays).
// ---------------------------------------------------------------------------
__global__ void big_kernel(const float* __restrict__ x_t,
                           const float4* __restrict__ gm4,
                           const float4* __restrict__ gm5,
                           const float4* __restrict__ gm6,
                           const float4* __restrict__ gm7,
                           float* __restrict__ out) {
    int v  = blockIdx.x * blockDim.x + threadIdx.x;  // float4 index, 0 .. 4194303
    int hv = v & (HH_ / 4 - 1);                      // h-vector index (0..127)
    int bd = v >> 7;                                 // combined b*512 + d index

    float4 gv = reinterpret_cast<const float4*>(g_arr)[hv];
    float4 pv = reinterpret_cast<const float4*>(phi_arr)[hv];
    float4 nv = reinterpret_cast<const float4*>(norm_arr)[hv];
    float  x  = __ldg(&x_t[bd]);

    float4 a4 = gm4[v];
    float4 a5 = gm5[v];
    float4 a6 = gm6[v];
    float4 a7 = gm7[v];

    float4 o4, o5, o6, o7;
    o4.x = gv.x * a4.x - pv.x * a5.x + nv.x * x;
    o4.y = gv.y * a4.y - pv.y * a5.y + nv.y * x;
    o4.z = gv.z * a4.z - pv.z * a5.z + nv.z * x;
    o4.w = gv.w * a4.w - pv.w * a5.w + nv.w * x;

    o5.x = gv.x * a5.x + pv.x * a4.x;
    o5.y = gv.y * a5.y + pv.y * a4.y;
    o5.z = gv.z * a5.z + pv.z * a4.z;
    o5.w = gv.w * a5.w + pv.w * a4.w;

    o6.x = gv.x * a6.x - pv.x * a7.x;
    o6.y = gv.y * a6.y - pv.y * a7.y;
    o6.z = gv.z * a6.z - pv.z * a7.z;
    o6.w = gv.w * a6.w - pv.w * a7.w;

    o7.x = gv.x * a7.x + pv.x * a6.x + nv.x * x;
    o7.y = gv.y * a7.y + pv.y * a6.y + nv.y * x;
    o7.z = gv.z * a7.z + pv.z * a6.z + nv.z * x;
    o7.w = gv.w * a7.w + pv.w * a6.w + nv.w * x;

    const int SMALL = 6 * BB_ * HH_;            // 196608 floats
    const int SZ    = BB_ * DIN_ * HH_;         // 16777216 floats
    float4* on4 = reinterpret_cast<float4*>(out + SMALL);
    float4* on5 = reinterpret_cast<float4*>(out + SMALL + SZ);
    float4* on6 = reinterpret_cast<float4*>(out + SMALL + 2 * SZ);
    float4* on7 = reinterpret_cast<float4*>(out + SMALL + 3 * SZ);

    on4[v] = o4;
    on5[v] = o5;
    on6[v] = o6;
    on7[v] = o7;
}

// ---------------------------------------------------------------------------
// Launch
// ---------------------------------------------------------------------------
extern "C" void kernel_launch(void* const* d_in, const int* in_sizes, int n_in,
                              void* d_out, int out_size) {
    const float* x_t   = (const float*)d_in[0];
    const float* h_c1  = (const float*)d_in[1];
    const float* h_c2  = (const float*)d_in[2];
    const float* gm0   = (const float*)d_in[3];
    const float* gm1   = (const float*)d_in[4];
    const float* gm2   = (const float*)d_in[5];
    const float* gm3   = (const float*)d_in[6];
    const float* gm4   = (const float*)d_in[7];
    const float* gm5   = (const float*)d_in[8];
    const float* gm6   = (const float*)d_in[9];
    const float* gm7   = (const float*)d_in[10];
    const float* r_p   = (const float*)d_in[11];
    const float* th_p  = (const float*)d_in[12];
    const float* wx1   = (const float*)d_in[13];
    const float* wx2   = (const float*)d_in[14];
    float* out = (float*)d_out;

    scalars_kernel<<<1, HH_>>>(r_p, th_p);

    dim3 g2(BB_ / 4, HH_ / 128);
    gemm_small_kernel<<<g2, 128>>>(x_t, h_c1, h_c2, gm0, gm1, gm2, gm3,
                                   r_p, th_p, wx1, wx2, out);

    const int NV = BB_ * DIN_ * HH_ / 4;  // 4,194,304 float4 elements
    big_kernel<<<NV / 256, 256>>>(x_t,
                                  (const float4*)gm4, (const float4*)gm5,
                                  (const float4*)gm6, (const float4*)gm7,
                                  out);
}

// round 2
// speedup vs baseline: 2.2838x; 2.2838x over previous
#include <cuda_runtime.h>

#define BB_   64
#define DIN_  512
#define HH_   512

#define GEMM_BLOCKS   32     // 16 b-tiles x 2 h-tiles
#define STREAM_BLOCKS 1184   // ~8 per SM on 148 SMs
#define NTHREADS      256

// ---------------------------------------------------------------------------
// Fused kernel:
//   blocks [0, GEMM_BLOCKS):             x@wx1, x@wx2 + epilogue -> h_t_c1,
//                                        h_t_c2, n0..n3 (B x H each)
//   blocks [GEMM_BLOCKS, +STREAM_BLOCKS): grid-stride streaming -> n4..n7
//                                        (B x D_IN x H each, HBM-bound)
// Disjoint output regions, no inter-path dependency.
// ---------------------------------------------------------------------------
__global__ void fused_kernel(const float* __restrict__ x_t,
                             const float* __restrict__ h_c1,
                             const float* __restrict__ h_c2,
                             const float* __restrict__ gm0,
                             const float* __restrict__ gm1,
                             const float* __restrict__ gm2,
                             const float* __restrict__ gm3,
                             const float4* __restrict__ gm4,
                             const float4* __restrict__ gm5,
                             const float4* __restrict__ gm6,
                             const float4* __restrict__ gm7,
                             const float* __restrict__ r_param,
                             const float* __restrict__ theta_param,
                             const float* __restrict__ wx1,
                             const float* __restrict__ wx2,
                             float* __restrict__ out) {
    __shared__ __align__(16) float sh[4 * DIN_];   // 8 KB, aliased per path

    const int tid = threadIdx.x;
    const int SZ_SMALL = BB_ * HH_;            // 32768
    const int SMALL    = 6 * SZ_SMALL;         // 196608 floats
    const int SZ_BIG   = BB_ * DIN_ * HH_;     // 16777216 floats

    if (blockIdx.x < GEMM_BLOCKS) {
        // ----------------- GEMM + small epilogue path -----------------
        const int BT = 4;
        const int bt = blockIdx.x >> 1;        // 0..15
        const int ht = blockIdx.x & 1;         // 0..1
        const int b0 = bt * BT;
        const int h  = ht * 256 + tid;         // each thread owns one h col

        float (*sx)[DIN_] = reinterpret_cast<float (*)[DIN_]>(sh);
        // stage 4 x_t rows (2048 floats) into smem, coalesced
        for (int i = tid; i < BT * DIN_; i += NTHREADS) {
            int bb = i >> 9;
            int d  = i & (DIN_ - 1);
            sx[bb][d] = x_t[(b0 + bb) * DIN_ + d];
        }
        __syncthreads();

        float acc1[BT] = {0.f, 0.f, 0.f, 0.f};
        float acc2[BT] = {0.f, 0.f, 0.f, 0.f};
#pragma unroll 8
        for (int d = 0; d < DIN_; d++) {
            float w1 = wx1[d * HH_ + h];
            float w2 = wx2[d * HH_ + h];
#pragma unroll
            for (int bb = 0; bb < BT; bb++) {
                float xv = sx[bb][d];
                acc1[bb] = fmaf(xv, w1, acc1[bb]);
                acc2[bb] = fmaf(xv, w2, acc2[bb]);
            }
        }

        // per-h scalars (one h per thread)
        float rp    = r_param[h];
        float tp    = theta_param[h];
        float exp_r = expf(rp);
        float r     = expf(-exp_r);
        float theta = expf(tp);
        float g     = r * cosf(theta);
        float phi   = r * sinf(theta);
        float rr    = r * r;
        float nrm   = sqrtf(1.0f - rr);
        float d_g_w_r       = -exp_r * g;
        float d_phi_w_r     = -exp_r * phi;
        float d_g_w_theta   = -theta * phi;
        float d_phi_w_theta =  theta * g;
        float d_norm_w_r    =  exp_r * rr / nrm;

#pragma unroll
        for (int bb = 0; bb < BT; bb++) {
            int idx = (b0 + bb) * HH_ + h;
            float hc1 = h_c1[idx];
            float hc2 = h_c2[idx];
            float m0 = gm0[idx], m1 = gm1[idx], m2 = gm2[idx], m3 = gm3[idx];
            float w1x = acc1[bb];
            float w2x = acc2[bb];

            out[0 * SZ_SMALL + idx] = g * hc1 - phi * hc2 + nrm * w1x;
            out[1 * SZ_SMALL + idx] = g * hc2 + phi * hc1 + nrm * w2x;
            out[2 * SZ_SMALL + idx] = d_g_w_r * hc1 + g * m0 - d_phi_w_r * hc2 - phi * m1 + d_norm_w_r * w1x;
            out[3 * SZ_SMALL + idx] = d_g_w_r * hc2 + g * m1 + d_phi_w_r * hc1 + phi * m0 + d_norm_w_r * w2x;
            out[4 * SZ_SMALL + idx] = d_g_w_theta * hc1 + g * m2 - d_phi_w_theta * hc2 - phi * m3;
            out[5 * SZ_SMALL + idx] = d_g_w_theta * hc2 + g * m3 + d_phi_w_theta * hc1 + phi * m2;
        }
    } else {
        // ----------------- HBM streaming path (n4..n7) -----------------
        float* sg = sh;            // [512]
        float* sp = sh + HH_;      // [512]
        float* sn = sh + 2 * HH_;  // [512]

        // each block computes all 512 h-scalar triples (2 per thread)
        for (int h = tid; h < HH_; h += NTHREADS) {
            float exp_r = expf(r_param[h]);
            float r     = expf(-exp_r);
            float theta = expf(theta_param[h]);
            sg[h] = r * cosf(theta);
            sp[h] = r * sinf(theta);
            sn[h] = sqrtf(1.0f - r * r);
        }
        __syncthreads();

        const float4* sg4 = reinterpret_cast<const float4*>(sg);
        const float4* sp4 = reinterpret_cast<const float4*>(sp);
        const float4* sn4 = reinterpret_cast<const float4*>(sn);

        float4* on4 = reinterpret_cast<float4*>(out + SMALL);
        float4* on5 = reinterpret_cast<float4*>(out + SMALL + SZ_BIG);
        float4* on6 = reinterpret_cast<float4*>(out + SMALL + 2 * SZ_BIG);
        float4* on7 = reinterpret_cast<float4*>(out + SMALL + 3 * SZ_BIG);

        const int NV     = BB_ * DIN_ * HH_ / 4;        // 4,194,304 float4
        const int stride = STREAM_BLOCKS * NTHREADS;
        int v = (blockIdx.x - GEMM_BLOCKS) * NTHREADS + tid;

        for (; v < NV; v += stride) {
            int hv = v & (HH_ / 4 - 1);
            int bd = v >> 7;

            float4 gv = sg4[hv];
            float4 pv = sp4[hv];
            float4 nv = sn4[hv];
            float  x  = __ldg(&x_t[bd]);

            float4 a4 = __ldcs(&gm4[v]);
            float4 a5 = __ldcs(&gm5[v]);
            float4 a6 = __ldcs(&gm6[v]);
            float4 a7 = __ldcs(&gm7[v]);

            float4 o4, o5, o6, o7;
            o4.x = gv.x * a4.x - pv.x * a5.x + nv.x * x;
            o4.y = gv.y * a4.y - pv.y * a5.y + nv.y * x;
            o4.z = gv.z * a4.z - pv.z * a5.z + nv.z * x;
            o4.w = gv.w * a4.w - pv.w * a5.w + nv.w * x;

            o5.x = gv.x * a5.x + pv.x * a4.x;
            o5.y = gv.y * a5.y + pv.y * a4.y;
            o5.z = gv.z * a5.z + pv.z * a4.z;
            o5.w = gv.w * a5.w + pv.w * a4.w;

            o6.x = gv.x * a6.x - pv.x * a7.x;
            o6.y = gv.y * a6.y - pv.y * a7.y;
            o6.z = gv.z * a6.z - pv.z * a7.z;
            o6.w = gv.w * a6.w - pv.w * a7.w;

            o7.x = gv.x * a7.x + pv.x * a6.x + nv.x * x;
            o7.y = gv.y * a7.y + pv.y * a6.y + nv.y * x;
            o7.z = gv.z * a7.z + pv.z * a6.z + nv.z * x;
            o7.w = gv.w * a7.w + pv.w * a6.w + nv.w * x;

            __stcs(&on4[v], o4);
            __stcs(&on5[v], o5);
            __stcs(&on6[v], o6);
            __stcs(&on7[v], o7);
        }
    }
}

// ---------------------------------------------------------------------------
// Launch: single kernel, single graph node.
// ---------------------------------------------------------------------------
extern "C" void kernel_launch(void* const* d_in, const int* in_sizes, int n_in,
                              void* d_out, int out_size) {
    const float* x_t   = (const float*)d_in[0];
    const float* h_c1  = (const float*)d_in[1];
    const float* h_c2  = (const float*)d_in[2];
    const float* gm0   = (const float*)d_in[3];
    const float* gm1   = (const float*)d_in[4];
    const float* gm2   = (const float*)d_in[5];
    const float* gm3   = (const float*)d_in[6];
    const float* gm4   = (const float*)d_in[7];
    const float* gm5   = (const float*)d_in[8];
    const float* gm6   = (const float*)d_in[9];
    const float* gm7   = (const float*)d_in[10];
    const float* r_p   = (const float*)d_in[11];
    const float* th_p  = (const float*)d_in[12];
    const float* wx1   = (const float*)d_in[13];
    const float* wx2   = (const float*)d_in[14];
    float* out = (float*)d_out;

    fused_kernel<<<GEMM_BLOCKS + STREAM_BLOCKS, NTHREADS>>>(
        x_t, h_c1, h_c2, gm0, gm1, gm2, gm3,
        (const float4*)gm4, (const float4*)gm5,
        (const float4*)gm6, (const float4*)gm7,
        r_p, th_p, wx1, wx2, out);
}

// round 3
// speedup vs baseline: 2.2937x; 1.0043x over previous
#include <cuda_runtime.h>

#define BB_   64
#define DIN_  512
#define HH_   512

#define GEMM_BLOCKS     32
#define STREAM_PER_HALF 428
#define STREAM_BLOCKS   (2 * STREAM_PER_HALF)   // 856
#define NTHREADS        256
// total grid = 888 = 148 SMs * 6 blocks -> single residency wave

__global__ void __launch_bounds__(NTHREADS, 6)
fused_kernel(const float* __restrict__ x_t,
             const float* __restrict__ h_c1,
             const float* __restrict__ h_c2,
             const float* __restrict__ gm0,
             const float* __restrict__ gm1,
             const float* __restrict__ gm2,
             const float* __restrict__ gm3,
             const float4* __restrict__ gm4,
             const float4* __restrict__ gm5,
             const float4* __restrict__ gm6,
             const float4* __restrict__ gm7,
             const float* __restrict__ r_param,
             const float* __restrict__ theta_param,
             const float* __restrict__ wx1,
             const float* __restrict__ wx2,
             float* __restrict__ out) {
    __shared__ __align__(16) float sh[4 * DIN_];   // 8 KB

    const int tid = threadIdx.x;
    const int SZ_SMALL = BB_ * HH_;            // 32768
    const int SMALL    = 6 * SZ_SMALL;         // 196608 floats
    const int SZ_BIG   = BB_ * DIN_ * HH_;     // 16777216 floats

    if (blockIdx.x < GEMM_BLOCKS) {
        // ----------------- GEMM + small epilogue path -----------------
        const int BT = 4;
        const int bt = blockIdx.x >> 1;
        const int ht = blockIdx.x & 1;
        const int b0 = bt * BT;
        const int h  = ht * 256 + tid;

        float (*sx)[DIN_] = reinterpret_cast<float (*)[DIN_]>(sh);
        for (int i = tid; i < BT * DIN_; i += NTHREADS) {
            int bb = i >> 9;
            int d  = i & (DIN_ - 1);
            sx[bb][d] = x_t[(b0 + bb) * DIN_ + d];
        }
        __syncthreads();

        float acc1[BT] = {0.f, 0.f, 0.f, 0.f};
        float acc2[BT] = {0.f, 0.f, 0.f, 0.f};
#pragma unroll 8
        for (int d = 0; d < DIN_; d++) {
            float w1 = wx1[d * HH_ + h];
            float w2 = wx2[d * HH_ + h];
#pragma unroll
            for (int bb = 0; bb < BT; bb++) {
                float xv = sx[bb][d];
                acc1[bb] = fmaf(xv, w1, acc1[bb]);
                acc2[bb] = fmaf(xv, w2, acc2[bb]);
            }
        }

        float rp    = r_param[h];
        float tp    = theta_param[h];
        float exp_r = expf(rp);
        float r     = expf(-exp_r);
        float theta = expf(tp);
        float g     = r * cosf(theta);
        float phi   = r * sinf(theta);
        float rr    = r * r;
        float nrm   = sqrtf(1.0f - rr);
        float d_g_w_r       = -exp_r * g;
        float d_phi_w_r     = -exp_r * phi;
        float d_g_w_theta   = -theta * phi;
        float d_phi_w_theta =  theta * g;
        float d_norm_w_r    =  exp_r * rr / nrm;

#pragma unroll
        for (int bb = 0; bb < BT; bb++) {
            int idx = (b0 + bb) * HH_ + h;
            float hc1 = h_c1[idx];
            float hc2 = h_c2[idx];
            float m0 = gm0[idx], m1 = gm1[idx], m2 = gm2[idx], m3 = gm3[idx];
            float w1x = acc1[bb];
            float w2x = acc2[bb];

            out[0 * SZ_SMALL + idx] = g * hc1 - phi * hc2 + nrm * w1x;
            out[1 * SZ_SMALL + idx] = g * hc2 + phi * hc1 + nrm * w2x;
            out[2 * SZ_SMALL + idx] = d_g_w_r * hc1 + g * m0 - d_phi_w_r * hc2 - phi * m1 + d_norm_w_r * w1x;
            out[3 * SZ_SMALL + idx] = d_g_w_r * hc2 + g * m1 + d_phi_w_r * hc1 + phi * m0 + d_norm_w_r * w2x;
            out[4 * SZ_SMALL + idx] = d_g_w_theta * hc1 + g * m2 - d_phi_w_theta * hc2 - phi * m3;
            out[5 * SZ_SMALL + idx] = d_g_w_theta * hc2 + g * m3 + d_phi_w_theta * hc1 + phi * m2;
        }
    } else {
        // ----------------- HBM streaming path -----------------
        // even stream-blocks: (gm4,gm5) -> (n4,n5); odd: (gm6,gm7) -> (n6,n7)
        float* sg = sh;
        float* sp = sh + HH_;
        float* sn = sh + 2 * HH_;

        for (int h = tid; h < HH_; h += NTHREADS) {
            float exp_r = expf(r_param[h]);
            float r     = expf(-exp_r);
            float theta = expf(theta_param[h]);
            sg[h] = r * cosf(theta);
            sp[h] = r * sinf(theta);
            sn[h] = sqrtf(1.0f - r * r);
        }
        __syncthreads();

        const float4* sg4 = reinterpret_cast<const float4*>(sg);
        const float4* sp4 = reinterpret_cast<const float4*>(sp);
        const float4* sn4 = reinterpret_cast<const float4*>(sn);

        const int sb   = blockIdx.x - GEMM_BLOCKS;
        const int half = sb & 1;
        const int sidx = sb >> 1;

        const float4* A  = half ? gm6 : gm4;
        const float4* Bp = half ? gm7 : gm5;
        float4* OA = reinterpret_cast<float4*>(out + SMALL + (half ? 2 : 0) * SZ_BIG);
        float4* OB = reinterpret_cast<float4*>(out + SMALL + (half ? 3 : 1) * SZ_BIG);
        const float selA = half ? 0.f : 1.f;   // n4 gets +norm*x
        const float selB = half ? 1.f : 0.f;   // n7 gets +norm*x

        const int NV     = BB_ * DIN_ * HH_ / 4;        // 4,194,304
        const int stride = STREAM_PER_HALF * NTHREADS;  // 109,568
        int v = sidx * NTHREADS + tid;

        // main loop: 2 slices in flight (4 LDG.128 outstanding per warp)
        for (; v + stride < NV; v += 2 * stride) {
            int v1 = v + stride;
            float4 a0 = __ldcs(&A[v]);
            float4 b0 = __ldcs(&Bp[v]);
            float4 a1 = __ldcs(&A[v1]);
            float4 b1 = __ldcs(&Bp[v1]);

            int hv0 = v  & (HH_ / 4 - 1);
            int hv1 = v1 & (HH_ / 4 - 1);
            float4 g0 = sg4[hv0], p0 = sp4[hv0], n0 = sn4[hv0];
            float4 g1 = sg4[hv1], p1 = sp4[hv1], n1 = sn4[hv1];
            float xa0 = selA * __ldg(&x_t[v  >> 7]);
            float xb0 = selB * __ldg(&x_t[v  >> 7]);
            float xa1 = selA * __ldg(&x_t[v1 >> 7]);
            float xb1 = selB * __ldg(&x_t[v1 >> 7]);

            float4 oa, ob;
            oa.x = g0.x * a0.x - p0.x * b0.x + n0.x * xa0;
            oa.y = g0.y * a0.y - p0.y * b0.y + n0.y * xa0;
            oa.z = g0.z * a0.z - p0.z * b0.z + n0.z * xa0;
            oa.w = g0.w * a0.w - p0.w * b0.w + n0.w * xa0;
            ob.x = g0.x * b0.x + p0.x * a0.x + n0.x * xb0;
            ob.y = g0.y * b0.y + p0.y * a0.y + n0.y * xb0;
            ob.z = g0.z * b0.z + p0.z * a0.z + n0.z * xb0;
            ob.w = g0.w * b0.w + p0.w * a0.w + n0.w * xb0;
            __stcs(&OA[v], oa);
            __stcs(&OB[v], ob);

            oa.x = g1.x * a1.x - p1.x * b1.x + n1.x * xa1;
            oa.y = g1.y * a1.y - p1.y * b1.y + n1.y * xa1;
            oa.z = g1.z * a1.z - p1.z * b1.z + n1.z * xa1;
            oa.w = g1.w * a1.w - p1.w * b1.w + n1.w * xa1;
            ob.x = g1.x * b1.x + p1.x * a1.x + n1.x * xb1;
            ob.y = g1.y * b1.y + p1.y * a1.y + n1.y * xb1;
            ob.z = g1.z * b1.z + p1.z * a1.z + n1.z * xb1;
            ob.w = g1.w * b1.w + p1.w * a1.w + n1.w * xb1;
            __stcs(&OA[v1], oa);
            __stcs(&OB[v1], ob);
        }
        if (v < NV) {
            float4 a0 = __ldcs(&A[v]);
            float4 b0 = __ldcs(&Bp[v]);
            int hv0 = v & (HH_ / 4 - 1);
            float4 g0 = sg4[hv0], p0 = sp4[hv0], n0 = sn4[hv0];
            float xa0 = selA * __ldg(&x_t[v >> 7]);
            float xb0 = selB * __ldg(&x_t[v >> 7]);

            float4 oa, ob;
            oa.x = g0.x * a0.x - p0.x * b0.x + n0.x * xa0;
            oa.y = g0.y * a0.y - p0.y * b0.y + n0.y * xa0;
            oa.z = g0.z * a0.z - p0.z * b0.z + n0.z * xa0;
            oa.w = g0.w * a0.w - p0.w * b0.w + n0.w * xa0;
            ob.x = g0.x * b0.x + p0.x * a0.x + n0.x * xb0;
            ob.y = g0.y * b0.y + p0.y * a0.y + n0.y * xb0;
            ob.z = g0.z * b0.z + p0.z * a0.z + n0.z * xb0;
            ob.w = g0.w * b0.w + p0.w * a0.w + n0.w * xb0;
            __stcs(&OA[v], oa);
            __stcs(&OB[v], ob);
        }
    }
}

extern "C" void kernel_launch(void* const* d_in, const int* in_sizes, int n_in,
                              void* d_out, int out_size) {
    const float* x_t   = (const float*)d_in[0];
    const float* h_c1  = (const float*)d_in[1];
    const float* h_c2  = (const float*)d_in[2];
    const float* gm0   = (const float*)d_in[3];
    const float* gm1   = (const float*)d_in[4];
    const float* gm2   = (const float*)d_in[5];
    const float* gm3   = (const float*)d_in[6];
    const float* gm4   = (const float*)d_in[7];
    const float* gm5   = (const float*)d_in[8];
    const float* gm6   = (const float*)d_in[9];
    const float* gm7   = (const float*)d_in[10];
    const float* r_p   = (const float*)d_in[11];
    const float* th_p  = (const float*)d_in[12];
    const float* wx1   = (const float*)d_in[13];
    const float* wx2   = (const float*)d_in[14];
    float* out = (float*)d_out;

    fused_kernel<<<GEMM_BLOCKS + STREAM_BLOCKS, NTHREADS>>>(
        x_t, h_c1, h_c2, gm0, gm1, gm2, gm3,
        (const float4*)gm4, (const float4*)gm5,
        (const float4*)gm6, (const float4*)gm7,
        r_p, th_p, wx1, wx2, out);
}

// round 4
// speedup vs baseline: 2.3972x; 1.0451x over previous
#include <cuda_runtime.h>

#define BB_   64
#define DIN_  512
#define HH_   512

#define GEMM_BLOCKS  32
#define TOTAL_BLOCKS 740        // 148 SMs * 5 blocks -> single wave
#define NTHREADS     256

#define CHUNK_V      2048       // float4 per chunk (aligned to 128-elem h period)
#define NV           (BB_ * DIN_ * HH_ / 4)       // 4,194,304 float4 per tensor
#define NCHUNK       (2 * (NV / CHUNK_V))         // 4096 chunks (2 halves)

__device__ int g_ctr  = 0;
__device__ int g_done = 0;

__global__ void __launch_bounds__(NTHREADS, 5)
fused_kernel(const float* __restrict__ x_t,
             const float* __restrict__ h_c1,
             const float* __restrict__ h_c2,
             const float* __restrict__ gm0,
             const float* __restrict__ gm1,
             const float* __restrict__ gm2,
             const float* __restrict__ gm3,
             const float4* __restrict__ gm4,
             const float4* __restrict__ gm5,
             const float4* __restrict__ gm6,
             const float4* __restrict__ gm7,
             const float* __restrict__ r_param,
             const float* __restrict__ theta_param,
             const float* __restrict__ wx1,
             const float* __restrict__ wx2,
             float* __restrict__ out) {
    __shared__ __align__(16) float sh[4 * DIN_];   // GEMM staging
    __shared__ int s_chunk;

    const int tid = threadIdx.x;
    const int SZ_SMALL = BB_ * HH_;            // 32768
    const int SMALL    = 6 * SZ_SMALL;         // 196608 floats
    const int SZ_BIG   = BB_ * DIN_ * HH_;     // 16777216 floats

    // ================= GEMM + small epilogue (blocks 0..31) =================
    if (blockIdx.x < GEMM_BLOCKS) {
        const int BT = 4;
        const int bt = blockIdx.x >> 1;
        const int ht = blockIdx.x & 1;
        const int b0 = bt * BT;
        const int h  = ht * 256 + tid;

        float (*sx)[DIN_] = reinterpret_cast<float (*)[DIN_]>(sh);
        for (int i = tid; i < BT * DIN_; i += NTHREADS) {
            int bb = i >> 9;
            int d  = i & (DIN_ - 1);
            sx[bb][d] = x_t[(b0 + bb) * DIN_ + d];
        }
        __syncthreads();

        float acc1[BT] = {0.f, 0.f, 0.f, 0.f};
        float acc2[BT] = {0.f, 0.f, 0.f, 0.f};
#pragma unroll 8
        for (int d = 0; d < DIN_; d++) {
            float w1 = wx1[d * HH_ + h];
            float w2 = wx2[d * HH_ + h];
#pragma unroll
            for (int bb = 0; bb < BT; bb++) {
                float xv = sx[bb][d];
                acc1[bb] = fmaf(xv, w1, acc1[bb]);
                acc2[bb] = fmaf(xv, w2, acc2[bb]);
            }
        }

        float exp_r = expf(r_param[h]);
        float r     = expf(-exp_r);
        float theta = expf(theta_param[h]);
        float g     = r * cosf(theta);
        float phi   = r * sinf(theta);
        float rr    = r * r;
        float nrm   = sqrtf(1.0f - rr);
        float d_g_w_r       = -exp_r * g;
        float d_phi_w_r     = -exp_r * phi;
        float d_g_w_theta   = -theta * phi;
        float d_phi_w_theta =  theta * g;
        float d_norm_w_r    =  exp_r * rr / nrm;

#pragma unroll
        for (int bb = 0; bb < BT; bb++) {
            int idx = (b0 + bb) * HH_ + h;
            float hc1 = h_c1[idx];
            float hc2 = h_c2[idx];
            float m0 = gm0[idx], m1 = gm1[idx], m2 = gm2[idx], m3 = gm3[idx];
            float w1x = acc1[bb];
            float w2x = acc2[bb];

            out[0 * SZ_SMALL + idx] = g * hc1 - phi * hc2 + nrm * w1x;
            out[1 * SZ_SMALL + idx] = g * hc2 + phi * hc1 + nrm * w2x;
            out[2 * SZ_SMALL + idx] = d_g_w_r * hc1 + g * m0 - d_phi_w_r * hc2 - phi * m1 + d_norm_w_r * w1x;
            out[3 * SZ_SMALL + idx] = d_g_w_r * hc2 + g * m1 + d_phi_w_r * hc1 + phi * m0 + d_norm_w_r * w2x;
            out[4 * SZ_SMALL + idx] = d_g_w_theta * hc1 + g * m2 - d_phi_w_theta * hc2 - phi * m3;
            out[5 * SZ_SMALL + idx] = d_g_w_theta * hc2 + g * m3 + d_phi_w_theta * hc1 + phi * m2;
        }
    }

    // ================= streaming: per-thread h scalars (registers) ==========
    // chunks are 2048 float4 = 16 * 128 h-vectors -> h vector index == tid&127
    const int h0 = (tid & 127) << 2;
    float4 gv, pv, nv;
    {
        float tg[4], tp_[4], tn[4];
#pragma unroll
        for (int k = 0; k < 4; k++) {
            float exp_r = expf(r_param[h0 + k]);
            float r     = expf(-exp_r);
            float theta = expf(theta_param[h0 + k]);
            tg[k]  = r * cosf(theta);
            tp_[k] = r * sinf(theta);
            tn[k]  = sqrtf(1.0f - r * r);
        }
        gv = make_float4(tg[0],  tg[1],  tg[2],  tg[3]);
        pv = make_float4(tp_[0], tp_[1], tp_[2], tp_[3]);
        nv = make_float4(tn[0],  tn[1],  tn[2],  tn[3]);
    }

    float4* outBig = reinterpret_cast<float4*>(out + SMALL);

    // ================= dynamic chunk-stealing loop ==========================
    for (;;) {
        if (tid == 0) s_chunk = atomicAdd(&g_ctr, 1);
        __syncthreads();
        const int c = s_chunk;
        if (c >= NCHUNK) break;

        const int   half = c & 1;
        const int   base = (c >> 1) * CHUNK_V + tid;
        const float4* A  = half ? gm6 : gm4;
        const float4* B  = half ? gm7 : gm5;
        float4* OA = outBig + (size_t)(half ? 2 : 0) * (SZ_BIG / 4);
        float4* OB = outBig + (size_t)(half ? 3 : 1) * (SZ_BIG / 4);
        const float selA = half ? 0.f : 1.f;   // n4 gets +norm*x
        const float selB = half ? 1.f : 0.f;   // n7 gets +norm*x

#pragma unroll
        for (int j = 0; j < 8; j += 2) {
            const int v0 = base + j * NTHREADS;
            const int v1 = v0 + NTHREADS;
            float4 a0 = __ldcs(A + v0);
            float4 b0 = __ldcs(B + v0);
            float4 a1 = __ldcs(A + v1);
            float4 b1 = __ldcs(B + v1);
            float x0 = __ldg(x_t + (v0 >> 7));
            float x1 = __ldg(x_t + (v1 >> 7));
            float xa0 = selA * x0, xb0 = selB * x0;
            float xa1 = selA * x1, xb1 = selB * x1;

            float4 oa, ob;
            oa.x = gv.x * a0.x - pv.x * b0.x + nv.x * xa0;
            oa.y = gv.y * a0.y - pv.y * b0.y + nv.y * xa0;
            oa.z = gv.z * a0.z - pv.z * b0.z + nv.z * xa0;
            oa.w = gv.w * a0.w - pv.w * b0.w + nv.w * xa0;
            ob.x = gv.x * b0.x + pv.x * a0.x + nv.x * xb0;
            ob.y = gv.y * b0.y + pv.y * a0.y + nv.y * xb0;
            ob.z = gv.z * b0.z + pv.z * a0.z + nv.z * xb0;
            ob.w = gv.w * b0.w + pv.w * a0.w + nv.w * xb0;
            __stcs(OA + v0, oa);
            __stcs(OB + v0, ob);

            oa.x = gv.x * a1.x - pv.x * b1.x + nv.x * xa1;
            oa.y = gv.y * a1.y - pv.y * b1.y + nv.y * xa1;
            oa.z = gv.z * a1.z - pv.z * b1.z + nv.z * xa1;
            oa.w = gv.w * a1.w - pv.w * b1.w + nv.w * xa1;
            ob.x = gv.x * b1.x + pv.x * a1.x + nv.x * xb1;
            ob.y = gv.y * b1.y + pv.y * a1.y + nv.y * xb1;
            ob.z = gv.z * b1.z + pv.z * a1.z + nv.z * xb1;
            ob.w = gv.w * b1.w + pv.w * a1.w + nv.w * xb1;
            __stcs(OA + v1, oa);
            __stcs(OB + v1, ob);
        }
        __syncthreads();   // protect s_chunk rewrite
    }

    // ================= counter reset (deterministic across replays) =========
    if (tid == 0) {
        __threadfence();
        int d = atomicAdd(&g_done, 1);
        if (d == (int)gridDim.x - 1) {
            g_ctr  = 0;
            g_done = 0;
            __threadfence();
        }
    }
}

extern "C" void kernel_launch(void* const* d_in, const int* in_sizes, int n_in,
                              void* d_out, int out_size) {
    const float* x_t   = (const float*)d_in[0];
    const float* h_c1  = (const float*)d_in[1];
    const float* h_c2  = (const float*)d_in[2];
    const float* gm0   = (const float*)d_in[3];
    const float* gm1   = (const float*)d_in[4];
    const float* gm2   = (const float*)d_in[5];
    const float* gm3   = (const float*)d_in[6];
    const float* gm4   = (const float*)d_in[7];
    const float* gm5   = (const float*)d_in[8];
    const float* gm6   = (const float*)d_in[9];
    const float* gm7   = (const float*)d_in[10];
    const float* r_p   = (const float*)d_in[11];
    const float* th_p  = (const float*)d_in[12];
    const float* wx1   = (const float*)d_in[13];
    const float* wx2   = (const float*)d_in[14];
    float* out = (float*)d_out;

    fused_kernel<<<TOTAL_BLOCKS, NTHREADS>>>(
        x_t, h_c1, h_c2, gm0, gm1, gm2, gm3,
        (const float4*)gm4, (const float4*)gm5,
        (const float4*)gm6, (const float4*)gm7,
        r_p, th_p, wx1, wx2, out);
}